// round 6
// baseline (speedup 1.0000x reference)
#include <cuda_runtime.h>

#define GN     128
#define GMASK  127
#define NCELLS (GN * GN * GN)

// grid scratch: [cell][2 float4] = 64 MB, plain z-major
__device__ float4 g_grid[NCELLS * 2];

// ---------------- P2G: 16 lanes/point, 2 points/warp (measured ~60us, LTS-atomic bound) ----
// lane layout: sub = lane>>4, k = lane&15, node = k>>1 (0..7), half = k&1.
__global__ __launch_bounds__(256)
void p2g_coop(const float* __restrict__ pos,
              const float4* __restrict__ feat4, int n) {
    int lane = threadIdx.x & 31;
    int warp = (blockIdx.x * blockDim.x + threadIdx.x) >> 5;
    int i = warp * 2 + (lane >> 4);
    if (i >= n) return;

    int k = lane & 15;
    int node = k >> 1;
    int half = k & 1;
    int ox = node >> 2, oy = (node >> 1) & 1, oz = node & 1;

    float rx = __ldg(&pos[3 * i + 0]) * (float)GN;
    float ry = __ldg(&pos[3 * i + 1]) * (float)GN;
    float rz = __ldg(&pos[3 * i + 2]) * (float)GN;
    int bx = (int)rx, by = (int)ry, bz = (int)rz;
    float fx = rx - (float)bx, fy = ry - (float)by, fz = rz - (float)bz;

    float w = (ox ? fx : 1.0f - fx) * (oy ? fy : 1.0f - fy) * (oz ? fz : 1.0f - fz);

    float4 f = __ldg(&feat4[2 * i + half]);

    int nx = (bx + ox) & GMASK;
    int ny = (by + oy) & GMASK;
    int nz = (bz + oz) & GMASK;
    int nid = ((nx << 7 | ny) << 7) | nz;

    float4 c = make_float4(w * f.x, w * f.y, w * f.z, w * f.w);
    atomicAdd(&g_grid[2 * nid + half], c);
}

// ---------------- G2P: 16 lanes/point, 2 points/warp ----------------
// lane = sub*16 + node*2 + half. Each lane loads ONE float4 (its half of its node's
// record), so every grid line is touched by exactly one LDG.128 instruction.
// Reduction over node bits (oz<->xor2, oy<->xor4, ox<->xor8) via halving exchange:
// 4 SHFLs total. Final: lanes with ox==0 (k<8) hold comp = half*4 + oz*2 + oy.
__global__ __launch_bounds__(256)
void g2p_coop16(const float* __restrict__ pos,
                float* __restrict__ out, int n) {
    int lane = threadIdx.x & 31;
    int warp = (blockIdx.x * blockDim.x + threadIdx.x) >> 5;
    int sub = lane >> 4;
    int i = warp * 2 + sub;
    bool active = (i < n);
    int ic = active ? i : (n - 1);   // keep lanes resident for shuffles

    int k = lane & 15;
    int node = k >> 1;
    int half = k & 1;
    int ox = node >> 2, oy = (node >> 1) & 1, oz = node & 1;

    float rx = __ldg(&pos[3 * ic + 0]) * (float)GN;
    float ry = __ldg(&pos[3 * ic + 1]) * (float)GN;
    float rz = __ldg(&pos[3 * ic + 2]) * (float)GN;
    int bx = (int)rx, by = (int)ry, bz = (int)rz;
    float fx = rx - (float)bx, fy = ry - (float)by, fz = rz - (float)bz;

    float w = (ox ? fx : 1.0f - fx) * (oy ? fy : 1.0f - fy) * (oz ? fz : 1.0f - fz);

    int nx = (bx + ox) & GMASK;
    int ny = (by + oy) & GMASK;
    int nz = (bz + oz) & GMASK;
    int nid = ((nx << 7 | ny) << 7) | nz;

    float4 g = __ldg(&g_grid[2 * nid + half]);
    float v0 = w * g.x, v1 = w * g.y, v2 = w * g.z, v3 = w * g.w;
    // lane holds comps {half*4+0 .. half*4+3} of its node's contribution

    bool soz = oz != 0, soy = oy != 0;
    float s, r;

    // Level A (xor 2, oz): halve 4 -> 2.  oz=0 keeps local comps {0,1}, oz=1 keeps {2,3}.
    float a0, a1;
    s = soz ? v0 : v2;  r = __shfl_xor_sync(0xffffffffu, s, 2);
    a0 = (soz ? v2 : v0) + r;
    s = soz ? v1 : v3;  r = __shfl_xor_sync(0xffffffffu, s, 2);
    a1 = (soz ? v3 : v1) + r;
    // lane holds comps {half*4 + oz*2 + 0, +1}

    // Level B (xor 4, oy): halve 2 -> 1. oy=0 keeps +0, oy=1 keeps +1.
    s = soy ? a0 : a1;  r = __shfl_xor_sync(0xffffffffu, s, 4);
    float b = (soy ? a1 : a0) + r;
    // lane holds comp = half*4 + oz*2 + oy

    // Level C (xor 8, ox): full exchange.
    b += __shfl_xor_sync(0xffffffffu, b, 8);

    // Store from ox==0 lanes: k in 0..7, comp = half*4 + oz*2 + oy (bit-reversal of k).
    if (active && ox == 0) {
        int comp = half * 4 + oz * 2 + oy;
        out[8 * (size_t)i + comp] = b;   // 2 pts/warp -> contiguous 64B per warp
    }
}

extern "C" void kernel_launch(void* const* d_in, const int* in_sizes, int n_in,
                              void* d_out, int out_size) {
    const float* pos  = (const float*)d_in[0];   // [N,3] f32
    const float* feat = (const float*)d_in[1];   // [N,8] f32
    float* out        = (float*)d_out;           // [N,8] f32
    int n = in_sizes[0] / 3;

    void* gptr = nullptr;
    cudaGetSymbolAddress(&gptr, g_grid);
    cudaMemsetAsync(gptr, 0, (size_t)NCELLS * 2 * sizeof(float4), 0);

    // 16 lanes/point: 16 points per 256-thread block, both kernels
    int blocks = (n + 15) / 16;
    p2g_coop<<<blocks, 256>>>(pos, (const float4*)feat, n);
    g2p_coop16<<<blocks, 256>>>(pos, (float*)out, n);
}

// round 7
// speedup vs baseline: 1.2172x; 1.2172x over previous
#include <cuda_runtime.h>

#define GN     128
#define GMASK  127
#define NCELLS (GN * GN * GN)

// grid scratch: [cell][2 float4] = 64 MB, plain z-major
__device__ float4 g_grid[NCELLS * 2];

// ---------------- P2G: 16 lanes/point, 2 points/warp (REDG-bound ~63us, keep) ----------------
// lane layout: sub = lane>>4, k = lane&15, node = k>>1 (0..7), half = k&1.
__global__ __launch_bounds__(256)
void p2g_coop(const float* __restrict__ pos,
              const float4* __restrict__ feat4, int n) {
    int lane = threadIdx.x & 31;
    int warp = (blockIdx.x * blockDim.x + threadIdx.x) >> 5;
    int i = warp * 2 + (lane >> 4);
    if (i >= n) return;

    int k = lane & 15;
    int node = k >> 1;
    int half = k & 1;
    int ox = node >> 2, oy = (node >> 1) & 1, oz = node & 1;

    float rx = __ldg(&pos[3 * i + 0]) * (float)GN;
    float ry = __ldg(&pos[3 * i + 1]) * (float)GN;
    float rz = __ldg(&pos[3 * i + 2]) * (float)GN;
    int bx = (int)rx, by = (int)ry, bz = (int)rz;
    float fx = rx - (float)bx, fy = ry - (float)by, fz = rz - (float)bz;

    float w = (ox ? fx : 1.0f - fx) * (oy ? fy : 1.0f - fy) * (oz ? fz : 1.0f - fz);

    float4 f = __ldg(&feat4[2 * i + half]);

    int nx = (bx + ox) & GMASK;
    int ny = (by + oy) & GMASK;
    int nz = (bz + oz) & GMASK;
    int nid = ((nx << 7 | ny) << 7) | nz;

    float4 c = make_float4(w * f.x, w * f.y, w * f.z, w * f.w);
    atomicAdd(&g_grid[2 * nid + half], c);
}

// ---------------- G2P: 8 lanes/point, 4 points/warp, ox-plane split loads ----------------
// lane = p*8 + s;  s bits: oy = bit2, oz = bit1, half = bit0.
// Load A: half-record `half` of node (0,oy,oz);  Load B: same for node (1,oy,oz).
// Each load instruction touches only its own ox-plane's lines -> ~4.5 lines/pt TOTAL.
// ox is summed in registers (v = wA*gA + wB*gB); butterfly reduces oz (xor2) and
// oy (xor4) in 3 SHFLs. Final: lane p*8+s holds comp = half*4 + oz*2 + oy, all 32
// lanes store -> one fully-coalesced 128B STG per warp.
__global__ __launch_bounds__(256)
void g2p_split(const float* __restrict__ pos,
               float* __restrict__ out, int n) {
    int lane = threadIdx.x & 31;
    int warp = (blockIdx.x * blockDim.x + threadIdx.x) >> 5;
    int p = lane >> 3;
    int s = lane & 7;
    int i = warp * 4 + p;
    bool active = (i < n);
    int ic = active ? i : (n - 1);   // keep lanes resident for shuffles

    int oy = (s >> 2) & 1;
    int oz = (s >> 1) & 1;
    int half = s & 1;

    float rx = __ldg(&pos[3 * ic + 0]) * (float)GN;
    float ry = __ldg(&pos[3 * ic + 1]) * (float)GN;
    float rz = __ldg(&pos[3 * ic + 2]) * (float)GN;
    int bx = (int)rx, by = (int)ry, bz = (int)rz;
    float fx = rx - (float)bx, fy = ry - (float)by, fz = rz - (float)bz;

    float wyz = (oy ? fy : 1.0f - fy) * (oz ? fz : 1.0f - fz);
    float wA = (1.0f - fx) * wyz;    // ox = 0
    float wB = fx * wyz;             // ox = 1

    int ny = (by + oy) & GMASK;
    int nz = (bz + oz) & GMASK;
    int nxA = bx & GMASK;
    int nxB = (bx + 1) & GMASK;
    int nidA = ((nxA << 7 | ny) << 7) | nz;
    int nidB = ((nxB << 7 | ny) << 7) | nz;

    float4 gA = __ldg(&g_grid[2 * nidA + half]);   // instr A: ox=0 plane only
    float4 gB = __ldg(&g_grid[2 * nidB + half]);   // instr B: ox=1 plane only

    // sum over ox in registers; lane holds comps half*4 + {0,1,2,3}
    float v0 = wA * gA.x + wB * gB.x;
    float v1 = wA * gA.y + wB * gB.y;
    float v2 = wA * gA.z + wB * gB.z;
    float v3 = wA * gA.w + wB * gB.w;

    bool soz = oz != 0, soy = oy != 0;
    float t, r;

    // Level oz (xor 2): halve 4 -> 2. oz=0 keeps comps +0,+1; oz=1 keeps +2,+3.
    float a0, a1;
    t = soz ? v0 : v2;  r = __shfl_xor_sync(0xffffffffu, t, 2);
    a0 = (soz ? v2 : v0) + r;
    t = soz ? v1 : v3;  r = __shfl_xor_sync(0xffffffffu, t, 2);
    a1 = (soz ? v3 : v1) + r;
    // lane holds comps half*4 + oz*2 + {0,1}

    // Level oy (xor 4): halve 2 -> 1. oy=0 keeps +0; oy=1 keeps +1.
    t = soy ? a0 : a1;  r = __shfl_xor_sync(0xffffffffu, t, 4);
    float b = (soy ? a1 : a0) + r;
    // lane holds comp = half*4 + oz*2 + oy

    if (active) {
        int comp = half * 4 + oz * 2 + oy;
        out[8 * (size_t)i + comp] = b;   // 32 lanes -> contiguous 128B per warp
    }
}

extern "C" void kernel_launch(void* const* d_in, const int* in_sizes, int n_in,
                              void* d_out, int out_size) {
    const float* pos  = (const float*)d_in[0];   // [N,3] f32
    const float* feat = (const float*)d_in[1];   // [N,8] f32
    float* out        = (float*)d_out;           // [N,8] f32
    int n = in_sizes[0] / 3;

    void* gptr = nullptr;
    cudaGetSymbolAddress(&gptr, g_grid);
    cudaMemsetAsync(gptr, 0, (size_t)NCELLS * 2 * sizeof(float4), 0);

    // p2g: 16 lanes/point -> 16 points per 256-thread block
    int pb = (n + 15) / 16;
    p2g_coop<<<pb, 256>>>(pos, (const float4*)feat, n);

    // g2p: 8 lanes/point -> 32 points per 256-thread block
    int gb = (n + 31) / 32;
    g2p_split<<<gb, 256>>>(pos, (float*)out, n);
}

// round 8
// speedup vs baseline: 1.3372x; 1.0986x over previous
#include <cuda_runtime.h>

#define GN     128
#define GMASK  127
#define NCELLS (GN * GN * GN)

// grid scratch: [cell][2 float4] = 64 MB, plain z-major
__device__ float4 g_grid[NCELLS * 2];

// ---------------- P2G: 16 lanes/point, 2 points/warp (at REDG lane-op floor ~63us) --------
__global__ __launch_bounds__(256)
void p2g_coop(const float* __restrict__ pos,
              const float4* __restrict__ feat4, int n) {
    int lane = threadIdx.x & 31;
    int warp = (blockIdx.x * blockDim.x + threadIdx.x) >> 5;
    int i = warp * 2 + (lane >> 4);
    if (i >= n) return;

    int k = lane & 15;
    int node = k >> 1;
    int half = k & 1;
    int ox = node >> 2, oy = (node >> 1) & 1, oz = node & 1;

    float rx = __ldg(&pos[3 * i + 0]) * (float)GN;
    float ry = __ldg(&pos[3 * i + 1]) * (float)GN;
    float rz = __ldg(&pos[3 * i + 2]) * (float)GN;
    int bx = (int)rx, by = (int)ry, bz = (int)rz;
    float fx = rx - (float)bx, fy = ry - (float)by, fz = rz - (float)bz;

    float w = (ox ? fx : 1.0f - fx) * (oy ? fy : 1.0f - fy) * (oz ? fz : 1.0f - fz);

    float4 f = __ldg(&feat4[2 * i + half]);

    int nx = (bx + ox) & GMASK;
    int ny = (by + oy) & GMASK;
    int nz = (bz + oz) & GMASK;
    int nid = ((nx << 7 | ny) << 7) | nz;

    float4 c = make_float4(w * f.x, w * f.y, w * f.z, w * f.w);
    atomicAdd(&g_grid[2 * nid + half], c);
}

// ---------------- G2P: 8 lanes/point, 2 points/THREAD (8 pts/warp), ox-plane split --------
// lane = p*8 + s;  s: oy=bit2, oz=bit1, half=bit0.  Thread handles points
// i0 = warp*8 + p and i1 = i0 + 4.  4 independent grid LDG.128 in flight.
// Butterfly reduces oz (xor2) then oy (xor4), carrying both points -> 6 SHFLs/thread.
// Final: lane holds comp = half*4 + oz*2 + oy for each point; two coalesced 128B stores.
struct PtCtx {
    float wA, wB;
    int nidA, nidB;
};

__device__ __forceinline__ PtCtx g2p_setup(const float* __restrict__ pos, int i,
                                           int oy, int oz) {
    float rx = __ldg(&pos[3 * i + 0]) * (float)GN;
    float ry = __ldg(&pos[3 * i + 1]) * (float)GN;
    float rz = __ldg(&pos[3 * i + 2]) * (float)GN;
    int bx = (int)rx, by = (int)ry, bz = (int)rz;
    float fx = rx - (float)bx, fy = ry - (float)by, fz = rz - (float)bz;

    float wyz = (oy ? fy : 1.0f - fy) * (oz ? fz : 1.0f - fz);
    PtCtx c;
    c.wA = (1.0f - fx) * wyz;
    c.wB = fx * wyz;
    int ny = (by + oy) & GMASK;
    int nz = (bz + oz) & GMASK;
    c.nidA = (((bx & GMASK) << 7 | ny) << 7) | nz;
    c.nidB = ((((bx + 1) & GMASK) << 7 | ny) << 7) | nz;
    return c;
}

__global__ __launch_bounds__(256)
void g2p_split2(const float* __restrict__ pos,
                float* __restrict__ out, int n) {
    int lane = threadIdx.x & 31;
    int warp = (blockIdx.x * blockDim.x + threadIdx.x) >> 5;
    int p = lane >> 3;
    int s = lane & 7;

    int i0 = warp * 8 + p;
    int i1 = i0 + 4;
    bool act0 = (i0 < n), act1 = (i1 < n);
    int ic0 = act0 ? i0 : (n - 1);
    int ic1 = act1 ? i1 : (n - 1);

    int oy = (s >> 2) & 1;
    int oz = (s >> 1) & 1;
    int half = s & 1;

    PtCtx c0 = g2p_setup(pos, ic0, oy, oz);
    PtCtx c1 = g2p_setup(pos, ic1, oy, oz);

    // 4 independent LDG.128 — max MLP before any dependent math
    float4 gA0 = __ldg(&g_grid[2 * c0.nidA + half]);
    float4 gB0 = __ldg(&g_grid[2 * c0.nidB + half]);
    float4 gA1 = __ldg(&g_grid[2 * c1.nidA + half]);
    float4 gB1 = __ldg(&g_grid[2 * c1.nidB + half]);

    // ox summed in registers
    float u0 = c0.wA * gA0.x + c0.wB * gB0.x;
    float u1 = c0.wA * gA0.y + c0.wB * gB0.y;
    float u2 = c0.wA * gA0.z + c0.wB * gB0.z;
    float u3 = c0.wA * gA0.w + c0.wB * gB0.w;
    float q0 = c1.wA * gA1.x + c1.wB * gB1.x;
    float q1 = c1.wA * gA1.y + c1.wB * gB1.y;
    float q2 = c1.wA * gA1.z + c1.wB * gB1.z;
    float q3 = c1.wA * gA1.w + c1.wB * gB1.w;

    bool soz = oz != 0, soy = oy != 0;
    float t, r;

    // Level oz (xor 2): halve 4 -> 2, both points
    float a0, a1, b0, b1;
    t = soz ? u0 : u2;  r = __shfl_xor_sync(0xffffffffu, t, 2);
    a0 = (soz ? u2 : u0) + r;
    t = soz ? u1 : u3;  r = __shfl_xor_sync(0xffffffffu, t, 2);
    a1 = (soz ? u3 : u1) + r;
    t = soz ? q0 : q2;  r = __shfl_xor_sync(0xffffffffu, t, 2);
    b0 = (soz ? q2 : q0) + r;
    t = soz ? q1 : q3;  r = __shfl_xor_sync(0xffffffffu, t, 2);
    b1 = (soz ? q3 : q1) + r;

    // Level oy (xor 4): halve 2 -> 1, both points
    t = soy ? a0 : a1;  r = __shfl_xor_sync(0xffffffffu, t, 4);
    float res0 = (soy ? a1 : a0) + r;
    t = soy ? b0 : b1;  r = __shfl_xor_sync(0xffffffffu, t, 4);
    float res1 = (soy ? b1 : b0) + r;

    int comp = half * 4 + oz * 2 + oy;
    if (act0) out[8 * (size_t)i0 + comp] = res0;  // lanes cover warp*64 + 0..31
    if (act1) out[8 * (size_t)i1 + comp] = res1;  // lanes cover warp*64 + 32..63
}

extern "C" void kernel_launch(void* const* d_in, const int* in_sizes, int n_in,
                              void* d_out, int out_size) {
    const float* pos  = (const float*)d_in[0];   // [N,3] f32
    const float* feat = (const float*)d_in[1];   // [N,8] f32
    float* out        = (float*)d_out;           // [N,8] f32
    int n = in_sizes[0] / 3;

    void* gptr = nullptr;
    cudaGetSymbolAddress(&gptr, g_grid);
    cudaMemsetAsync(gptr, 0, (size_t)NCELLS * 2 * sizeof(float4), 0);

    // p2g: 16 lanes/point -> 16 points per 256-thread block
    int pb = (n + 15) / 16;
    p2g_coop<<<pb, 256>>>(pos, (const float4*)feat, n);

    // g2p: 8 lanes/point, 2 pts/thread -> 64 points per 256-thread block
    int gb = (n + 63) / 64;
    g2p_split2<<<gb, 256>>>(pos, (float*)out, n);
}